// round 16
// baseline (speedup 1.0000x reference)
// MoEExperts round 16: fp16 m16n8k16 packed-fragment GEMM with a WARP-
// AUTONOMOUS pipeline: each warp owns a private 16KB smem region (4 stages x
// 4KB) and loads exactly the A-half/B-half it consumes. No __syncthreads in
// the main loop (cross-warp smem visibility never needed) -> warps drift out
// of phase and cover each other's LDS/loop heads on the SMSP tensor pipe,
// which round 15 showed was the ~220cyc/iter stall (barrier-aligned LDS
// bursts). Cost: 2x fill traffic (L2 22%->~45%, far from cap).
// CTA 128x128 (4 warps 64x64), 64KB smem total, register-local fused silu
// epilogue emitting hid in fp16 A-frag layout, fp32 accumulate.

#include <cuda_runtime.h>
#include <cuda_fp16.h>
#include <cstdint>

#define Tt 4096
#define Ee 8
#define Hh 1024
#define Qq 1024

// Packed fp16 scratch (uint4 = 8 halves = one lane-fragment).
__device__ uint4 g_xr [ 524288];   //  8 MB  x      [mt=256][kt= 64][lane]
__device__ uint4 g_w1p[2097152];   // 32 MB  W1     [e][npt=128][kt=64][lane]
__device__ uint4 g_dnr[1048576];   // 16 MB  down   [npt=64][kt=512][lane]
__device__ uint4 g_hid[4194304];   // 64 MB  hidden [mt=256][kt=512][lane]

// ---------------------------------------------------------------- helpers
__device__ __forceinline__ unsigned smem_u32(const void* p) {
    return (unsigned)__cvta_generic_to_shared(p);
}
__device__ __forceinline__ void cp_async16(unsigned s, const void* g) {
    asm volatile("cp.async.cg.shared.global [%0], [%1], 16;\n" :: "r"(s), "l"(g));
}
__device__ __forceinline__ void cp_commit() {
    asm volatile("cp.async.commit_group;\n");
}
template<int N>
__device__ __forceinline__ void cp_wait() {
    asm volatile("cp.async.wait_group %0;\n" :: "n"(N));
}
// pack two floats -> f16x2 (round-to-nearest), lo = first arg
__device__ __forceinline__ unsigned h2(float a, float b) {
    __half2 h = __floats2half2_rn(a, b);
    return *reinterpret_cast<unsigned*>(&h);
}
__device__ __forceinline__ void mma_f16(float* c, const uint4& a,
                                        unsigned b0, unsigned b1) {
    asm volatile(
        "mma.sync.aligned.m16n8k16.row.col.f32.f16.f16.f32 "
        "{%0,%1,%2,%3}, {%4,%5,%6,%7}, {%8,%9}, {%0,%1,%2,%3};\n"
        : "+f"(c[0]), "+f"(c[1]), "+f"(c[2]), "+f"(c[3])
        : "r"(a.x), "r"(a.y), "r"(a.z), "r"(a.w), "r"(b0), "r"(b1));
}

// ---------------------------------------------------------------- GEMM
// CTA 128m x 128n; 4 warps 2x2, warp tile 64x64. Warp-private staging:
// stage = 1 k-tile (k=16): A 4 mt x 512B = 2KB + B 4 npt x 512B = 2KB.
// 4 stages x 4KB = 16KB per warp; 64KB per CTA; 2 CTAs/SM.
constexpr int WSTG     = 4096;             // bytes per warp-stage
constexpr int WREG     = 4 * WSTG;         // 16KB per warp
constexpr int SMEM_TOT = 4 * WREG;         // 65,536 B

template<bool FUSE>
__global__ __launch_bounds__(128, 2)
void gemm_f16(const uint4* __restrict__ A,     // [mt][kt][lane]
              const uint4* __restrict__ B,     // [npt][kt][lane]
              long long sBe,                    // uint4 per expert (B)
              const float* __restrict__ rw,
              void* __restrict__ Cv,            // FUSE: uint4 hid; else float out
              int KT)                           // K/16 tiles
{
    extern __shared__ char smem[];

    const int tid = threadIdx.x;
    const int lane = tid & 31, warp = tid >> 5;
    const int wm = warp >> 1, wn = warp & 1;      // 2x2 warp grid
    const int gid = lane >> 2, tig = lane & 3;

    const int nb = blockIdx.x;               // n-block (128 cols = 8 npt)
    const int by = blockIdx.y;               // m-block (128 rows = 8 mt)
    const int e  = blockIdx.z;

    // This warp's operands: 4 A m-tiles (its wm half), 4 B n-pair tiles (wn).
    const uint4* Awm = A + (size_t)(by * 8 + wm * 4) * KT * 32;
    const uint4* Bwn = B + (size_t)e * sBe + (size_t)(nb * 8 + wn * 4) * KT * 32;

    char* ws = smem + warp * WREG;           // warp-private staging

    const int nIter = KT;                    // 1 k-tile per iteration

    auto load_stage = [&](int it) {
        char* s = ws + (it & 3) * WSTG;
        #pragma unroll
        for (int im = 0; im < 4; im++)
            cp_async16(smem_u32(s + (im * 32 + lane) * 16),
                       Awm + ((size_t)im * KT + it) * 32 + lane);
        #pragma unroll
        for (int p = 0; p < 4; p++)
            cp_async16(smem_u32(s + 2048 + (p * 32 + lane) * 16),
                       Bwn + ((size_t)p * KT + it) * 32 + lane);
        cp_commit();
    };

    float acc[4][8][4];
    #pragma unroll
    for (int im = 0; im < 4; im++)
        #pragma unroll
        for (int in = 0; in < 8; in++)
            #pragma unroll
            for (int v = 0; v < 4; v++) acc[im][in][v] = 0.f;

    load_stage(0);
    load_stage(1);
    load_stage(2);

    for (int it = 0; it < nIter; ++it) {
        if      (it + 2 < nIter) cp_wait<2>();   // stage `it` complete
        else if (it + 1 < nIter) cp_wait<1>();
        else                     cp_wait<0>();
        __syncwarp();
        if (it + 3 < nIter) load_stage(it + 3);  // slot (it-1)&3: own reads done

        const char* s = ws + (it & 3) * WSTG;
        uint4 va[4], vb[4];
        #pragma unroll
        for (int im = 0; im < 4; im++)
            va[im] = *(const uint4*)(s + (im * 32 + lane) * 16);
        #pragma unroll
        for (int p = 0; p < 4; p++)
            vb[p] = *(const uint4*)(s + 2048 + (p * 32 + lane) * 16);
        #pragma unroll
        for (int im = 0; im < 4; im++)
            #pragma unroll
            for (int p = 0; p < 4; p++) {
                mma_f16(acc[im][2 * p],     va[im], vb[p].x, vb[p].y);
                mma_f16(acc[im][2 * p + 1], va[im], vb[p].z, vb[p].w);
            }
    }
    // Epilogue uses no shared memory; warps finish independently.

    // acc[im][in]: rows by*128 + wm*64 + im*16 + gid (+8),
    // cols nb*128 + wn*64 + in*8 + {2tig, 2tig+1}.
    if constexpr (FUSE) {
        // 64-block = [gate32|up32] of q-range (nb*2+wn)*32; in<4 gate, in+4 up.
        #pragma unroll
        for (int im = 0; im < 4; im++) {
            const int r = wm * 64 + im * 16 + gid;
            const int t0 = by * 128 + r;
            const float w0 = rw[t0 * Ee + e];
            const float w1 = rw[(t0 + 8) * Ee + e];
            const size_t mt = (size_t)(by * 8 + wm * 4 + im);
            float hv[4][4];
            #pragma unroll
            for (int in = 0; in < 4; in++) {
                float g, u;
                g = acc[im][in][0]; u = acc[im][in + 4][0];
                hv[in][0] = w0 * u * (g / (1.f + __expf(-g)));
                g = acc[im][in][1]; u = acc[im][in + 4][1];
                hv[in][1] = w0 * u * (g / (1.f + __expf(-g)));
                g = acc[im][in][2]; u = acc[im][in + 4][2];
                hv[in][2] = w1 * u * (g / (1.f + __expf(-g)));
                g = acc[im][in][3]; u = acc[im][in + 4][3];
                hv[in][3] = w1 * u * (g / (1.f + __expf(-g)));
            }
            // two fp16 A-frags (k-tiles s=0,1) for k3
            #pragma unroll
            for (int s = 0; s < 2; s++) {
                uint4 o;
                o.x = h2(hv[2 * s][0],     hv[2 * s][1]);
                o.y = h2(hv[2 * s][2],     hv[2 * s][3]);
                o.z = h2(hv[2 * s + 1][0], hv[2 * s + 1][1]);
                o.w = h2(hv[2 * s + 1][2], hv[2 * s + 1][3]);
                const size_t ktile = (size_t)(e * 64 + (nb * 2 + wn) * 2 + s);
                ((uint4*)Cv)[(mt * 512 + ktile) * 32 + lane] = o;
            }
        }
    } else {
        float* C = (float*)Cv;
        #pragma unroll
        for (int im = 0; im < 4; im++) {
            const int r = wm * 64 + im * 16 + gid;
            const int t0 = by * 128 + r;
            #pragma unroll
            for (int in = 0; in < 8; in++) {
                const int col = nb * 128 + wn * 64 + in * 8 + 2 * tig;
                *(float2*)&C[(size_t)t0 * Hh + col] =
                    make_float2(acc[im][in][0], acc[im][in][1]);
                *(float2*)&C[(size_t)(t0 + 8) * Hh + col] =
                    make_float2(acc[im][in][2], acc[im][in][3]);
            }
        }
    }
}

// ---------------------------------------------------------------- prepass
// pack_a: x (4096x1024) -> fp16 A-frags [mt=256][kt=64][lane].
__global__ void pack_a(const float* __restrict__ x, uint4* __restrict__ dst)
{
    const int idx = blockIdx.x * blockDim.x + threadIdx.x;   // 524288
    const int lane = idx & 31, kt = (idx >> 5) & 63, mt = idx >> 11;
    const int g = lane >> 2, t = lane & 3;
    const int m = mt * 16 + g, k = kt * 16 + 2 * t;
    const float* x0 = x + (size_t)m * 1024 + k;
    const float* x8 = x + (size_t)(m + 8) * 1024 + k;
    uint4 o;
    o.x = h2(x0[0], x0[1]);
    o.y = h2(x8[0], x8[1]);
    o.z = h2(x0[8], x0[9]);
    o.w = h2(x8[8], x8[9]);
    dst[idx] = o;
}

// pack_w1: gup (E,H,2Q) -> fp16 B n-pair frags in permuted n' space
// (n' 64-block = [gate32|up32]): [e][npt=128][kt=64][lane].
__global__ void pack_w1(const float* __restrict__ gup, uint4* __restrict__ dst)
{
    const int idx = blockIdx.x * blockDim.x + threadIdx.x;   // 2097152
    const int lane = idx & 31, kt = (idx >> 5) & 63, npt = (idx >> 11) & 127;
    const int e = idx >> 18;
    const int g = lane >> 2, t = lane & 3;
    const int k = kt * 16 + 2 * t;
    auto orig = [](int np) {
        const int b = np >> 6, i = np & 63;
        return (i < 32) ? b * 32 + i : 1024 + b * 32 + (i - 32);
    };
    const int nA = orig(npt * 16 + g);
    const int nB = orig(npt * 16 + 8 + g);
    const float* base = gup + ((size_t)e * 1024 + k) * 2048;   // row stride 2048
    uint4 o;
    o.x = h2(base[nA],            base[2048 + nA]);            // k, k+1 @ nA
    o.y = h2(base[8 * 2048 + nA], base[9 * 2048 + nA]);        // k+8,k+9 @ nA
    o.z = h2(base[nB],            base[2048 + nB]);
    o.w = h2(base[8 * 2048 + nB], base[9 * 2048 + nB]);
    dst[idx] = o;
}

// pack_dn: down (E,Q,H) flattened (8192 x 1024) -> fp16 B n-pair frags
// [npt=64][kt=512][lane] (k = e*1024+q).
__global__ void pack_dn(const float* __restrict__ dn, uint4* __restrict__ dst)
{
    const int idx = blockIdx.x * blockDim.x + threadIdx.x;   // 1048576
    const int lane = idx & 31, kt = (idx >> 5) & 511, npt = idx >> 14;
    const int g = lane >> 2, t = lane & 3;
    const int k = kt * 16 + 2 * t;
    const int n = npt * 16 + g;
    const float* base = dn + (size_t)k * 1024 + n;
    uint4 o;
    o.x = h2(base[0],            base[1024]);
    o.y = h2(base[8 * 1024],     base[9 * 1024]);
    o.z = h2(base[8],            base[1024 + 8]);
    o.w = h2(base[8 * 1024 + 8], base[9 * 1024 + 8]);
    dst[idx] = o;
}

// ---------------------------------------------------------------- launch
extern "C" void kernel_launch(void* const* d_in, const int* in_sizes, int n_in,
                              void* d_out, int out_size)
{
    (void)in_sizes; (void)n_in; (void)out_size;
    const float* x    = (const float*)d_in[0];   // (T, H)
    const float* rw   = (const float*)d_in[1];   // (T, E)
    const float* gup  = (const float*)d_in[2];   // (E, H, 2Q)
    const float* down = (const float*)d_in[3];   // (E, Q, H)
    float* out = (float*)d_out;                  // (T, H)

    uint4 *xr, *w1p, *dnr, *hid;
    cudaGetSymbolAddress((void**)&xr,  g_xr);
    cudaGetSymbolAddress((void**)&w1p, g_w1p);
    cudaGetSymbolAddress((void**)&dnr, g_dnr);
    cudaGetSymbolAddress((void**)&hid, g_hid);

    cudaFuncSetAttribute(gemm_f16<true>,
                         cudaFuncAttributeMaxDynamicSharedMemorySize, SMEM_TOT);
    cudaFuncSetAttribute(gemm_f16<false>,
                         cudaFuncAttributeMaxDynamicSharedMemorySize, SMEM_TOT);

    pack_a <<<2048, 256>>>(x, xr);
    pack_w1<<<8192, 256>>>(gup, w1p);
    pack_dn<<<4096, 256>>>(down, dnr);

    // k1: hidden = rw * silu(gate) * up (fused, fp16 A-frag store). KT=64.
    gemm_f16<true><<<dim3(16, 32, 8), 128, SMEM_TOT>>>(
        xr, w1p, 262144LL, rw, hid, 64);

    // k3: out = hid(4096x8192) @ dnr^T. KT=512. grid (8, 32) = 256 CTAs.
    gemm_f16<false><<<dim3(8, 32, 1), 128, SMEM_TOT>>>(
        hid, dnr, 0LL, nullptr, out, 512);
}